// round 2
// baseline (speedup 1.0000x reference)
#include <cuda_runtime.h>

// Problem constants (fixed shapes)
#define B_  4096
#define N_  64
#define H_  128
#define E_  1024

// ---------------------------------------------------------------------------
// Device-global scratch (alloc-free workaround; 128MB flat buffer + tiny CSR)
// ---------------------------------------------------------------------------
__device__ int   g_off[N_ + 1];
__device__ int   g_srcl[E_];
__device__ float g_wl[E_];
__device__ float g_s1[N_];
__device__ float g_u[H_];
__device__ float g_c[H_];
__device__ float g_hf[(size_t)B_ * N_ * H_];   // 128 MB: final h_flat

// ---------------------------------------------------------------------------
// Prep kernel: edge-index dtype sniffing (int32 vs int64), deterministic CSR
// by dst, and rank-1 layer-0 folding (u, c, s1). One block, 256 threads.
// ---------------------------------------------------------------------------
__global__ void prep_kernel(const void* __restrict__ ei_raw,
                            const float* __restrict__ ea,
                            const float* __restrict__ w_enc,
                            const float* __restrict__ b_enc,
                            const float* __restrict__ Wl,
                            const float* __restrict__ bl)
{
    __shared__ int   s_dst[E_];
    __shared__ int   s_src[E_];
    __shared__ float s_w[E_];
    __shared__ int   s_cnt[N_];
    __shared__ int   s_off[N_ + 1];
    __shared__ int   s_is64;

    const int* e32 = (const int*)ei_raw;
    int t = threadIdx.x;

    // dtype sniff: int64 little-endian values < 64 => every odd int32 slot of
    // the first 2048 is zero. Genuine int32 data has edge values there.
    if (t == 0) {
        int all0 = 1;
        for (int i = 1; i < 2 * E_; i += 2)
            if (e32[i] != 0) { all0 = 0; break; }
        s_is64 = all0;
    }
    __syncthreads();
    const int is64 = s_is64;

    for (int e = t; e < E_; e += blockDim.x) {
        s_src[e] = is64 ? e32[2 * e]          : e32[e];
        s_dst[e] = is64 ? e32[2 * (E_ + e)]   : e32[E_ + e];
        s_w[e]   = ea[e];
    }
    __syncthreads();

    if (t < N_) {
        int cnt = 0; float sum = 0.f;
        for (int e = 0; e < E_; e++)
            if (s_dst[e] == t) { cnt++; sum += s_w[e]; }
        s_cnt[t] = cnt;
        g_s1[t] = sum;
    }
    __syncthreads();

    if (t == 0) {
        int run = 0;
        for (int d = 0; d < N_; d++) { s_off[d] = run; run += s_cnt[d]; }
        s_off[N_] = run;
    }
    __syncthreads();

    if (t < N_) {
        int p = s_off[t];
        for (int e = 0; e < E_; e++)
            if (s_dst[e] == t) { g_srcl[p] = s_src[e]; g_wl[p] = s_w[e]; p++; }
    }
    if (t <= N_) g_off[t] = s_off[t];

    // u = w_enc @ W0 ; c = b_enc @ W0 + b0   (layer-0 rank-1 fold)
    if (t < H_) {
        float su = 0.f, sc = 0.f;
        for (int h = 0; h < H_; h++) {
            float wv = Wl[h * H_ + t];
            su += w_enc[h] * wv;
            sc += b_enc[h] * wv;
        }
        g_u[t] = su;
        g_c[t] = sc + bl[t];
    }
}

// ---------------------------------------------------------------------------
// Fused GNN kernel: one CTA per batch element.
// h (64x128) lives in SMEM across all 3 layers. Layer 0 via rank-1 shortcut,
// layers 1,2 as SMEM GEMM (64x128x128) + CSR message pass + residual ReLU.
// Final h_flat written to g_hf.
// ---------------------------------------------------------------------------
__global__ __launch_bounds__(256) void gnn_kernel(
    const float* __restrict__ x,
    const float* __restrict__ w_enc,
    const float* __restrict__ b_enc,
    const float* __restrict__ Wl,
    const float* __restrict__ bl)
{
    extern __shared__ float sm[];
    float* sh_h  = sm;                 // 64*128
    float* sh_hn = sm + 8192;          // 64*128
    float* sh_xr = sm + 16384;         // 64
    float* sh_g  = sh_xr + 64;         // 64
    float* sh_s1 = sh_g  + 64;         // 64
    float* sh_we = sh_s1 + 64;         // 128
    float* sh_be = sh_we + 128;        // 128
    float* sh_u  = sh_be + 128;        // 128
    float* sh_c  = sh_u  + 128;        // 128

    const int b = blockIdx.x;
    const int t = threadIdx.x;

    if (t < 64) { sh_xr[t] = x[b * 64 + t]; sh_s1[t] = g_s1[t]; }
    if (t >= 128) {
        int k = t - 128;
        sh_we[k] = w_enc[k]; sh_be[k] = b_enc[k];
        sh_u[k]  = g_u[k];   sh_c[k]  = g_c[k];
    }
    __syncthreads();

    // g[d] = (A x)[d]
    if (t < 64) {
        float acc = 0.f;
        int e0 = g_off[t], e1 = g_off[t + 1];
        for (int e = e0; e < e1; e++) acc += g_wl[e] * sh_xr[g_srcl[e]];
        sh_g[t] = acc;
    }
    __syncthreads();

    // Layer 0 (rank-1 shortcut): h = relu(x*we + be + g*u + s1*c)
    for (int idx = t; idx < 8192; idx += 256) {
        int n = idx >> 7, k = idx & 127;
        float v = sh_xr[n] * sh_we[k] + sh_be[k] + sh_g[n] * sh_u[k] + sh_s1[n] * sh_c[k];
        sh_h[idx] = fmaxf(v, 0.f);
    }
    __syncthreads();

    const int warp = t >> 5, lane = t & 31;
    const int r0 = warp * 8;    // 8 warps x 8 rows = 64
    const int c0 = lane * 4;    // 32 lanes x 4 cols = 128

    for (int l = 1; l < 3; l++) {
        const float* W = Wl + l * H_ * H_;
        const float4 b4 = *(const float4*)(bl + l * H_ + c0);
        float acc[8][4];
        #pragma unroll
        for (int i = 0; i < 8; i++) {
            acc[i][0] = b4.x; acc[i][1] = b4.y; acc[i][2] = b4.z; acc[i][3] = b4.w;
        }
        // hn = h @ W + b : A from SMEM (float4 broadcast), W from global (L1-resident)
        for (int k = 0; k < 128; k += 4) {
            float4 a4[8];
            #pragma unroll
            for (int i = 0; i < 8; i++)
                a4[i] = *(const float4*)&sh_h[(r0 + i) * 128 + k];
            #pragma unroll
            for (int kk = 0; kk < 4; kk++) {
                float4 wv = __ldg((const float4*)(W + (k + kk) * 128 + c0));
                #pragma unroll
                for (int i = 0; i < 8; i++) {
                    float a = (kk == 0) ? a4[i].x : (kk == 1) ? a4[i].y
                            : (kk == 2) ? a4[i].z : a4[i].w;
                    acc[i][0] += a * wv.x; acc[i][1] += a * wv.y;
                    acc[i][2] += a * wv.z; acc[i][3] += a * wv.w;
                }
            }
        }
        #pragma unroll
        for (int i = 0; i < 8; i++)
            *(float4*)&sh_hn[(r0 + i) * 128 + c0] =
                make_float4(acc[i][0], acc[i][1], acc[i][2], acc[i][3]);
        __syncthreads();

        // h = relu(h + scatter-add messages)
        for (int idx = t; idx < 8192; idx += 256) {
            int d = idx >> 7, k = idx & 127;
            float a = sh_h[idx];
            int e0 = g_off[d], e1 = g_off[d + 1];
            for (int e = e0; e < e1; e++)
                a += g_wl[e] * sh_hn[g_srcl[e] * 128 + k];
            sh_h[idx] = fmaxf(a, 0.f);
        }
        __syncthreads();
    }

    const size_t base = (size_t)b * 8192;
    for (int idx = t; idx < 8192; idx += 256)
        g_hf[base + idx] = sh_h[idx];
}

// ---------------------------------------------------------------------------
// Classifier: hidden = relu(h_flat @ Wc1 + bc1); logits = hidden @ Wc2 + bc2
// Tiled GEMM: 32-row batch tile x full 128 cols, K=8192 in 32-chunks with
// register-prefetch double buffering. Grid = 128 CTAs, 256 threads.
// ---------------------------------------------------------------------------
__global__ __launch_bounds__(256) void cls_kernel(
    const float* __restrict__ Wc1, const float* __restrict__ bc1,
    const float* __restrict__ Wc2, const float* __restrict__ bc2,
    float* __restrict__ out)
{
    __shared__ float As[32 * 32];    // A tile [m][kk]
    __shared__ float Bs[32 * 128];   // B tile [kk][c] (reused as hidden)

    const int t = threadIdx.x;
    const int m0 = blockIdx.x * 32;
    const int warp = t >> 5, lane = t & 31;
    const int r0 = warp * 4;   // 8 warps x 4 rows = 32
    const int c0 = lane * 4;   // 32 lanes x 4 cols = 128

    float acc[4][4];
    #pragma unroll
    for (int i = 0; i < 4; i++)
        for (int j = 0; j < 4; j++) acc[i][j] = 0.f;

    const int am  = t >> 3, akk = t & 7;           // A load map: float4 #t
    float4 pa;
    float4 pb[4];

    pa = *(const float4*)&g_hf[(size_t)(m0 + am) * 8192 + akk * 4];
    #pragma unroll
    for (int i = 0; i < 4; i++) {
        int f = t + i * 256, kk = f >> 5, c4 = f & 31;
        pb[i] = __ldg((const float4*)&Wc1[(size_t)kk * 128 + c4 * 4]);
    }

    for (int k0 = 0; k0 < 8192; k0 += 32) {
        // commit prefetched tile
        *(float4*)&As[am * 32 + akk * 4] = pa;
        #pragma unroll
        for (int i = 0; i < 4; i++) {
            int f = t + i * 256, kk = f >> 5, c4 = f & 31;
            *(float4*)&Bs[kk * 128 + c4 * 4] = pb[i];
        }
        __syncthreads();

        // prefetch next tile (overlaps with compute below)
        int k1 = k0 + 32;
        if (k1 < 8192) {
            pa = *(const float4*)&g_hf[(size_t)(m0 + am) * 8192 + k1 + akk * 4];
            #pragma unroll
            for (int i = 0; i < 4; i++) {
                int f = t + i * 256, kk = f >> 5, c4 = f & 31;
                pb[i] = __ldg((const float4*)&Wc1[(size_t)(k1 + kk) * 128 + c4 * 4]);
            }
        }

        #pragma unroll
        for (int kk4 = 0; kk4 < 8; kk4++) {
            float4 a4[4];
            #pragma unroll
            for (int i = 0; i < 4; i++)
                a4[i] = *(const float4*)&As[(r0 + i) * 32 + kk4 * 4];
            #pragma unroll
            for (int kk = 0; kk < 4; kk++) {
                float4 b4 = *(const float4*)&Bs[(kk4 * 4 + kk) * 128 + c0];
                #pragma unroll
                for (int i = 0; i < 4; i++) {
                    float a = (kk == 0) ? a4[i].x : (kk == 1) ? a4[i].y
                            : (kk == 2) ? a4[i].z : a4[i].w;
                    acc[i][0] += a * b4.x; acc[i][1] += a * b4.y;
                    acc[i][2] += a * b4.z; acc[i][3] += a * b4.w;
                }
            }
        }
        __syncthreads();
    }

    // hidden = relu(acc + bc1) -> Bs (reused), then tiny 128x2 matvec
    float4 bb = __ldg((const float4*)(bc1 + c0));
    #pragma unroll
    for (int i = 0; i < 4; i++) {
        float4 v = make_float4(fmaxf(acc[i][0] + bb.x, 0.f),
                               fmaxf(acc[i][1] + bb.y, 0.f),
                               fmaxf(acc[i][2] + bb.z, 0.f),
                               fmaxf(acc[i][3] + bb.w, 0.f));
        *(float4*)&Bs[(r0 + i) * 128 + c0] = v;
    }
    __syncthreads();

    if (t < 64) {
        int r = t >> 1, o = t & 1;
        float s = bc2[o];
        #pragma unroll 4
        for (int k = 0; k < 128; k++)
            s += Bs[r * 128 + k] * __ldg(&Wc2[k * 2 + o]);
        out[(m0 + r) * 2 + o] = s;
    }
}

// ---------------------------------------------------------------------------
// Launch
// ---------------------------------------------------------------------------
extern "C" void kernel_launch(void* const* d_in, const int* in_sizes, int n_in,
                              void* d_out, int out_size)
{
    const float* x     = (const float*)d_in[0];
    const void*  ei    = d_in[1];                 // int32 or int64, sniffed on device
    const float* ea    = (const float*)d_in[2];
    const float* w_enc = (const float*)d_in[3];
    const float* b_enc = (const float*)d_in[4];
    const float* Wl    = (const float*)d_in[5];
    const float* bl    = (const float*)d_in[6];
    const float* Wc1   = (const float*)d_in[7];
    const float* bc1   = (const float*)d_in[8];
    const float* Wc2   = (const float*)d_in[9];
    const float* bc2   = (const float*)d_in[10];
    float* out = (float*)d_out;

    const int gnn_smem = (16384 + 3 * 64 + 4 * 128) * (int)sizeof(float); // 68352 B
    cudaFuncSetAttribute(gnn_kernel, cudaFuncAttributeMaxDynamicSharedMemorySize,
                         gnn_smem);

    prep_kernel<<<1, 256>>>(ei, ea, w_enc, b_enc, Wl, bl);
    gnn_kernel<<<B_, 256, gnn_smem>>>(x, w_enc, b_enc, Wl, bl);
    cls_kernel<<<B_ / 32, 256>>>(Wc1, bc1, Wc2, bc2, out);
}

// round 3
// speedup vs baseline: 1.1433x; 1.1433x over previous
#include <cuda_runtime.h>

// Problem constants (fixed shapes)
#define B_  4096
#define N_  64
#define H_  128
#define E_  1024

typedef unsigned long long ull;

// ---------------------------------------------------------------------------
// Packed f32x2 helpers (Blackwell FFMA2 path — PTX-only)
// ---------------------------------------------------------------------------
__device__ __forceinline__ ull fma2(ull a, ull b, ull c) {
    ull d;
    asm("fma.rn.f32x2 %0, %1, %2, %3;" : "=l"(d) : "l"(a), "l"(b), "l"(c));
    return d;
}
__device__ __forceinline__ ull pack2(float v) {
    ull d;
    asm("mov.b64 %0, {%1, %1};" : "=l"(d) : "f"(v));
    return d;
}
__device__ __forceinline__ ull packpair(float lo, float hi) {
    ull d;
    asm("mov.b64 %0, {%1, %2};" : "=l"(d) : "f"(lo), "f"(hi));
    return d;
}
__device__ __forceinline__ void unpack2(ull v, float& lo, float& hi) {
    asm("mov.b64 {%0, %1}, %2;" : "=f"(lo), "=f"(hi) : "l"(v));
}

// ---------------------------------------------------------------------------
// Device-global scratch (alloc-free workaround)
// ---------------------------------------------------------------------------
__device__ int   g_off[N_ + 1];
__device__ int   g_srcl[E_];
__device__ float g_wl[E_];
__device__ float g_s1[N_];
__device__ float g_u[H_];
__device__ float g_c[H_];
__device__ float g_hf[(size_t)B_ * N_ * H_];   // 128 MB: final h_flat

// ---------------------------------------------------------------------------
// Prep: parallel int32/int64 sniff, deterministic CSR by dst, rank-1 fold.
// ---------------------------------------------------------------------------
__global__ void prep_kernel(const void* __restrict__ ei_raw,
                            const float* __restrict__ ea,
                            const float* __restrict__ w_enc,
                            const float* __restrict__ b_enc,
                            const float* __restrict__ Wl,
                            const float* __restrict__ bl)
{
    __shared__ int   s_dst[E_];
    __shared__ int   s_src[E_];
    __shared__ float s_w[E_];
    __shared__ int   s_cnt[N_];
    __shared__ int   s_off[N_ + 1];
    __shared__ int   s_flag;

    const int* e32 = (const int*)ei_raw;
    int t = threadIdx.x;

    if (t == 0) s_flag = 0;
    __syncthreads();

    // int64 little-endian values < 64  =>  every odd int32 slot is zero.
    int any = 0;
    for (int i = 1 + 2 * t; i < 2 * E_; i += 2 * blockDim.x)
        any |= (e32[i] != 0);
    if (any) atomicOr(&s_flag, 1);
    __syncthreads();
    const int is64 = (s_flag == 0);

    for (int e = t; e < E_; e += blockDim.x) {
        s_src[e] = is64 ? e32[2 * e]        : e32[e];
        s_dst[e] = is64 ? e32[2 * (E_ + e)] : e32[E_ + e];
        s_w[e]   = ea[e];
    }
    __syncthreads();

    if (t < N_) {
        int cnt = 0; float sum = 0.f;
        for (int e = 0; e < E_; e++)
            if (s_dst[e] == t) { cnt++; sum += s_w[e]; }
        s_cnt[t] = cnt;
        g_s1[t] = sum;
    }
    __syncthreads();

    if (t == 0) {
        int run = 0;
        for (int d = 0; d < N_; d++) { s_off[d] = run; run += s_cnt[d]; }
        s_off[N_] = run;
    }
    __syncthreads();

    if (t < N_) {
        int p = s_off[t];
        for (int e = 0; e < E_; e++)
            if (s_dst[e] == t) { g_srcl[p] = s_src[e]; g_wl[p] = s_w[e]; p++; }
    }
    if (t <= N_) g_off[t] = s_off[t];

    // u = w_enc @ W0 ; c = b_enc @ W0 + b0   (layer-0 rank-1 fold)
    if (t < H_) {
        float su = 0.f, sc = 0.f;
        for (int h = 0; h < H_; h++) {
            float wv = Wl[h * H_ + t];
            su += w_enc[h] * wv;
            sc += b_enc[h] * wv;
        }
        g_u[t] = su;
        g_c[t] = sc + bl[t];
    }
}

// ---------------------------------------------------------------------------
// Fused GNN: one CTA per batch element. h resident in SMEM across all layers.
// GEMM + message pass use packed f32x2 FMA; CSR cached in SMEM.
// SMEM: 2*32KB h/hn + 768B vecs + CSR(off 260B, srcl 4KB, wl 4KB) ~= 73KB
// => 3 CTAs/SM.
// ---------------------------------------------------------------------------
__global__ __launch_bounds__(256) void gnn_kernel(
    const float* __restrict__ x,
    const float* __restrict__ w_enc,
    const float* __restrict__ b_enc,
    const float* __restrict__ Wl,
    const float* __restrict__ bl)
{
    extern __shared__ float sm[];
    float* sh_h  = sm;                      // 8192
    float* sh_hn = sm + 8192;               // 8192
    float* sh_xr = sm + 16384;              // 64
    float* sh_g  = sh_xr + 64;              // 64
    float* sh_s1 = sh_g  + 64;              // 64
    float* sh_wl = sh_s1 + 64;              // 1024
    int*   sh_off  = (int*)(sh_wl + 1024);  // 65
    int*   sh_srcl = sh_off + 68;           // 1024 (68: keep 16B align slack)

    const int b = blockIdx.x;
    const int t = threadIdx.x;

    if (t < 64) { sh_xr[t] = x[b * 64 + t]; sh_s1[t] = g_s1[t]; }
    if (t <= N_) sh_off[t] = g_off[t];
    #pragma unroll
    for (int i = 0; i < 4; i++) {
        int e = t + i * 256;
        sh_srcl[e] = g_srcl[e];
        sh_wl[e]   = g_wl[e];
    }
    __syncthreads();

    // g[d] = (A x)[d]
    if (t < 64) {
        float acc = 0.f;
        int e0 = sh_off[t], e1 = sh_off[t + 1];
        for (int e = e0; e < e1; e++) acc += sh_wl[e] * sh_xr[sh_srcl[e]];
        sh_g[t] = acc;
    }
    __syncthreads();

    // Layer 0 (rank-1 shortcut): h = relu(x*we + be + g*u + s1*c)
    for (int idx = t; idx < 8192; idx += 256) {
        int n = idx >> 7, k = idx & 127;
        float v = sh_xr[n] * __ldg(&w_enc[k]) + __ldg(&b_enc[k])
                + sh_g[n] * __ldg(&g_u[k]) + sh_s1[n] * __ldg(&g_c[k]);
        sh_h[idx] = fmaxf(v, 0.f);
    }
    __syncthreads();

    const int warp = t >> 5, lane = t & 31;
    const int r0 = warp * 8;    // 8 warps x 8 rows = 64
    const int c0 = lane * 4;    // 32 lanes x 4 cols = 128

    for (int l = 1; l < 3; l++) {
        const float* W = Wl + l * H_ * H_;
        // bias as packed col-pairs
        ulonglong2 bz = *(const ulonglong2*)(bl + l * H_ + c0);
        ull acc0[8], acc1[8];
        #pragma unroll
        for (int i = 0; i < 8; i++) { acc0[i] = bz.x; acc1[i] = bz.y; }

        // hn = h @ W + b : A via SMEM broadcast, W from global (L1), FFMA2
        for (int k = 0; k < 128; k += 4) {
            float4 a4[8];
            #pragma unroll
            for (int i = 0; i < 8; i++)
                a4[i] = *(const float4*)&sh_h[(r0 + i) * 128 + k];
            #pragma unroll
            for (int kk = 0; kk < 4; kk++) {
                ulonglong2 w2 = *(const ulonglong2*)(W + (k + kk) * 128 + c0);
                #pragma unroll
                for (int i = 0; i < 8; i++) {
                    float a = (kk == 0) ? a4[i].x : (kk == 1) ? a4[i].y
                            : (kk == 2) ? a4[i].z : a4[i].w;
                    ull ap = pack2(a);
                    acc0[i] = fma2(ap, w2.x, acc0[i]);
                    acc1[i] = fma2(ap, w2.y, acc1[i]);
                }
            }
        }
        #pragma unroll
        for (int i = 0; i < 8; i++) {
            ulonglong2 v; v.x = acc0[i]; v.y = acc1[i];
            *(ulonglong2*)&sh_hn[(r0 + i) * 128 + c0] = v;
        }
        __syncthreads();

        // h = relu(h + A @ hn), packed over k-pairs; d warp-uniform => CSR
        // loads are SMEM broadcasts.
        #pragma unroll
        for (int it = 0; it < 16; it++) {
            int idx2 = t + it * 256;          // 0..4095
            int d = idx2 >> 6, kp = idx2 & 63;
            ull acc = *(ull*)&sh_h[d * 128 + kp * 2];
            int e0 = sh_off[d], e1 = sh_off[d + 1];
            for (int e = e0; e < e1; e++) {
                ull w2 = pack2(sh_wl[e]);
                acc = fma2(w2, *(ull*)&sh_hn[sh_srcl[e] * 128 + kp * 2], acc);
            }
            float lo, hi; unpack2(acc, lo, hi);
            *(ull*)&sh_h[d * 128 + kp * 2] =
                packpair(fmaxf(lo, 0.f), fmaxf(hi, 0.f));
        }
        __syncthreads();
    }

    const size_t base = (size_t)b * 8192;
    #pragma unroll
    for (int i = 0; i < 8; i++) {
        int f = t + i * 256;                  // float4 index
        *(float4*)&g_hf[base + f * 4] = *(const float4*)&sh_h[f * 4];
    }
}

// ---------------------------------------------------------------------------
// Classifier: hidden = relu(h_flat @ Wc1 + bc1); logits = hidden @ Wc2 + bc2
// 32-row x 128-col tiles, K=8192 in 32-chunks, register double-buffering,
// packed f32x2 inner product. Grid = 128 CTAs, 256 threads.
// ---------------------------------------------------------------------------
__global__ __launch_bounds__(256) void cls_kernel(
    const float* __restrict__ Wc1, const float* __restrict__ bc1,
    const float* __restrict__ Wc2, const float* __restrict__ bc2,
    float* __restrict__ out)
{
    __shared__ float As[32 * 32];    // A tile [m][kk]
    __shared__ float Bs[32 * 128];   // B tile [kk][c] (reused as hidden)

    const int t = threadIdx.x;
    const int m0 = blockIdx.x * 32;
    const int warp = t >> 5, lane = t & 31;
    const int r0 = warp * 4;   // 8 warps x 4 rows = 32
    const int c0 = lane * 4;   // 32 lanes x 4 cols = 128

    ull acc0[4], acc1[4];
    #pragma unroll
    for (int i = 0; i < 4; i++) { acc0[i] = 0ull; acc1[i] = 0ull; }

    const int am = t >> 3, akk = t & 7;           // A load map: float4 #t
    float4 pa;
    float4 pb[4];

    pa = *(const float4*)&g_hf[(size_t)(m0 + am) * 8192 + akk * 4];
    #pragma unroll
    for (int i = 0; i < 4; i++) {
        int f = t + i * 256, kk = f >> 5, c4 = f & 31;
        pb[i] = __ldg((const float4*)&Wc1[(size_t)kk * 128 + c4 * 4]);
    }

    for (int k0 = 0; k0 < 8192; k0 += 32) {
        // commit prefetched tile
        *(float4*)&As[am * 32 + akk * 4] = pa;
        #pragma unroll
        for (int i = 0; i < 4; i++) {
            int f = t + i * 256, kk = f >> 5, c4 = f & 31;
            *(float4*)&Bs[kk * 128 + c4 * 4] = pb[i];
        }
        __syncthreads();

        // prefetch next tile (overlaps with compute below)
        int k1 = k0 + 32;
        if (k1 < 8192) {
            pa = *(const float4*)&g_hf[(size_t)(m0 + am) * 8192 + k1 + akk * 4];
            #pragma unroll
            for (int i = 0; i < 4; i++) {
                int f = t + i * 256, kk = f >> 5, c4 = f & 31;
                pb[i] = __ldg((const float4*)&Wc1[(size_t)(k1 + kk) * 128 + c4 * 4]);
            }
        }

        #pragma unroll
        for (int kk4 = 0; kk4 < 8; kk4++) {
            float4 a4[4];
            #pragma unroll
            for (int i = 0; i < 4; i++)
                a4[i] = *(const float4*)&As[(r0 + i) * 32 + kk4 * 4];
            #pragma unroll
            for (int kk = 0; kk < 4; kk++) {
                ulonglong2 b2 = *(const ulonglong2*)&Bs[(kk4 * 4 + kk) * 128 + c0];
                #pragma unroll
                for (int i = 0; i < 4; i++) {
                    float a = (kk == 0) ? a4[i].x : (kk == 1) ? a4[i].y
                            : (kk == 2) ? a4[i].z : a4[i].w;
                    ull ap = pack2(a);
                    acc0[i] = fma2(ap, b2.x, acc0[i]);
                    acc1[i] = fma2(ap, b2.y, acc1[i]);
                }
            }
        }
        __syncthreads();
    }

    // hidden = relu(acc + bc1) -> Bs (reused), then tiny 128x2 matvec
    float4 bb = __ldg((const float4*)(bc1 + c0));
    #pragma unroll
    for (int i = 0; i < 4; i++) {
        float x0, x1, x2, x3;
        unpack2(acc0[i], x0, x1);
        unpack2(acc1[i], x2, x3);
        float4 v = make_float4(fmaxf(x0 + bb.x, 0.f), fmaxf(x1 + bb.y, 0.f),
                               fmaxf(x2 + bb.z, 0.f), fmaxf(x3 + bb.w, 0.f));
        *(float4*)&Bs[(r0 + i) * 128 + c0] = v;
    }
    __syncthreads();

    if (t < 64) {
        int r = t >> 1, o = t & 1;
        float s = bc2[o];
        #pragma unroll 4
        for (int k = 0; k < 128; k++)
            s += Bs[r * 128 + k] * __ldg(&Wc2[k * 2 + o]);
        out[(m0 + r) * 2 + o] = s;
    }
}

// ---------------------------------------------------------------------------
// Launch
// ---------------------------------------------------------------------------
extern "C" void kernel_launch(void* const* d_in, const int* in_sizes, int n_in,
                              void* d_out, int out_size)
{
    const float* x     = (const float*)d_in[0];
    const void*  ei    = d_in[1];                 // int32 or int64, sniffed
    const float* ea    = (const float*)d_in[2];
    const float* w_enc = (const float*)d_in[3];
    const float* b_enc = (const float*)d_in[4];
    const float* Wl    = (const float*)d_in[5];
    const float* bl    = (const float*)d_in[6];
    const float* Wc1   = (const float*)d_in[7];
    const float* bc1   = (const float*)d_in[8];
    const float* Wc2   = (const float*)d_in[9];
    const float* bc2   = (const float*)d_in[10];
    float* out = (float*)d_out;

    // floats: 8192+8192+64+64+64+1024 = 17600 ; ints: 68+1024 = 1092
    const int gnn_smem = (17600 + 1092) * (int)sizeof(float);   // 74768 B
    cudaFuncSetAttribute(gnn_kernel, cudaFuncAttributeMaxDynamicSharedMemorySize,
                         gnn_smem);

    prep_kernel<<<1, 256>>>(ei, ea, w_enc, b_enc, Wl, bl);
    gnn_kernel<<<B_, 256, gnn_smem>>>(x, w_enc, b_enc, Wl, bl);
    cls_kernel<<<B_ / 32, 256>>>(Wc1, bc1, Wc2, bc2, out);
}

// round 5
// speedup vs baseline: 1.5993x; 1.3988x over previous
#include <cuda_runtime.h>
#include <cuda_bf16.h>
#include <cstdint>

// Problem constants (fixed shapes)
#define B_  4096
#define N_  64
#define H_  128
#define E_  1024
#define P_  132   // sh_h row pitch (floats): stride%32=4 -> <=2-way LDS conflicts

typedef unsigned long long ull;
typedef unsigned short u16;
typedef unsigned int u32;

// ---------------------------------------------------------------------------
// Helpers
// ---------------------------------------------------------------------------
__device__ __forceinline__ u32 smem_u32(const void* p) {
    u32 a;
    asm("{ .reg .u64 t; cvta.to.shared.u64 t, %1; cvt.u32.u64 %0, t; }"
        : "=r"(a) : "l"(p));
    return a;
}
// pack two fp32 -> bf16x2 (e0 -> low half, e1 -> high half), round-nearest
__device__ __forceinline__ u32 packbf(float e0, float e1) {
    u32 r;
    asm("cvt.rn.bf16x2.f32 %0, %1, %2;" : "=r"(r) : "f"(e1), "f"(e0));
    return r;
}
// hi/lo split of a pair
__device__ __forceinline__ void split2(float e0, float e1, u32& hi, u32& lo) {
    hi = packbf(e0, e1);
    float h0 = __uint_as_float(hi << 16);
    float h1 = __uint_as_float(hi & 0xffff0000u);
    lo = packbf(e0 - h0, e1 - h1);
}
__device__ __forceinline__ void mma_bf16(float& c0, float& c1, float& c2, float& c3,
                                         u32 a0, u32 a1, u32 a2, u32 a3,
                                         u32 b0, u32 b1) {
    asm volatile(
        "mma.sync.aligned.m16n8k16.row.col.f32.bf16.bf16.f32 "
        "{%0,%1,%2,%3}, {%4,%5,%6,%7}, {%8,%9}, {%0,%1,%2,%3};"
        : "+f"(c0), "+f"(c1), "+f"(c2), "+f"(c3)
        : "r"(a0), "r"(a1), "r"(a2), "r"(a3), "r"(b0), "r"(b1));
}
__device__ __forceinline__ void ldmx4(u32& r0, u32& r1, u32& r2, u32& r3, u32 addr) {
    asm volatile("ldmatrix.sync.aligned.m8n8.x4.shared.b16 {%0,%1,%2,%3}, [%4];"
                 : "=r"(r0), "=r"(r1), "=r"(r2), "=r"(r3) : "r"(addr));
}
// packed f32x2 fma (legalized to 2xFFMA on sm_100; keeps code compact)
__device__ __forceinline__ ull fma2(ull a, ull b, ull c) {
    ull d;
    asm("fma.rn.f32x2 %0, %1, %2, %3;" : "=l"(d) : "l"(a), "l"(b), "l"(c));
    return d;
}
__device__ __forceinline__ ull pack2(float v) {
    ull d; asm("mov.b64 %0, {%1, %1};" : "=l"(d) : "f"(v)); return d;
}
__device__ __forceinline__ ull packpair(float lo, float hi) {
    ull d; asm("mov.b64 %0, {%1, %2};" : "=l"(d) : "f"(lo), "f"(hi)); return d;
}
__device__ __forceinline__ void unpack2(ull v, float& lo, float& hi) {
    asm("mov.b64 {%0, %1}, %2;" : "=f"(lo), "=f"(hi) : "l"(v));
}

// ---------------------------------------------------------------------------
// Device-global scratch (alloc-free workaround)
// ---------------------------------------------------------------------------
__device__ int   g_off[N_ + 1];
__device__ int   g_srcl[E_];
__device__ float g_wl[E_];
__device__ float g_s1[N_];
__device__ float g_u[H_];
__device__ float g_c[H_];
__device__ u16   g_ahi[(size_t)B_ * N_ * H_];   // 64 MB bf16 hi of h_flat [m][k]
__device__ u16   g_alo[(size_t)B_ * N_ * H_];   // 64 MB bf16 lo
__device__ u16   g_bhi[(size_t)H_ * 8192];      // Wc1^T hi: [n=128][k=8192]
__device__ u16   g_blo[(size_t)H_ * 8192];      // Wc1^T lo
__device__ u16   g_wthi[2 * H_ * H_];           // W^T (layers 1,2) hi: [l][n][k]
__device__ u16   g_wtlo[2 * H_ * H_];           // lo
__device__ float g_part[(size_t)256 * 64 * 128]; // split-K partials (8 MB)

// ---------------------------------------------------------------------------
// Prep: dtype sniff, deterministic CSR, rank-1 layer-0 fold, W^T bf16 split.
// ---------------------------------------------------------------------------
__global__ void prep_kernel(const void* __restrict__ ei_raw,
                            const float* __restrict__ ea,
                            const float* __restrict__ w_enc,
                            const float* __restrict__ b_enc,
                            const float* __restrict__ Wl,
                            const float* __restrict__ bl)
{
    __shared__ int   s_dst[E_];
    __shared__ int   s_src[E_];
    __shared__ float s_w[E_];
    __shared__ int   s_cnt[N_];
    __shared__ int   s_off[N_ + 1];
    __shared__ int   s_flag;

    const int* e32 = (const int*)ei_raw;
    int t = threadIdx.x;

    if (t == 0) s_flag = 0;
    __syncthreads();
    int any = 0;
    for (int i = 1 + 2 * t; i < 2 * E_; i += 2 * blockDim.x)
        any |= (e32[i] != 0);
    if (any) atomicOr(&s_flag, 1);
    __syncthreads();
    const int is64 = (s_flag == 0);

    for (int e = t; e < E_; e += blockDim.x) {
        s_src[e] = is64 ? e32[2 * e]        : e32[e];
        s_dst[e] = is64 ? e32[2 * (E_ + e)] : e32[E_ + e];
        s_w[e]   = ea[e];
    }
    __syncthreads();

    if (t < N_) {
        int cnt = 0; float sum = 0.f;
        for (int e = 0; e < E_; e++)
            if (s_dst[e] == t) { cnt++; sum += s_w[e]; }
        s_cnt[t] = cnt;
        g_s1[t] = sum;
    }
    __syncthreads();

    if (t == 0) {
        int run = 0;
        for (int d = 0; d < N_; d++) { s_off[d] = run; run += s_cnt[d]; }
        s_off[N_] = run;
    }
    __syncthreads();

    if (t < N_) {
        int p = s_off[t];
        for (int e = 0; e < E_; e++)
            if (s_dst[e] == t) { g_srcl[p] = s_src[e]; g_wl[p] = s_w[e]; p++; }
    }
    if (t <= N_) g_off[t] = s_off[t];

    if (t < H_) {
        float su = 0.f, sc = 0.f;
        for (int h = 0; h < H_; h++) {
            float wv = Wl[h * H_ + t];
            su += w_enc[h] * wv;
            sc += b_enc[h] * wv;
        }
        g_u[t] = su;
        g_c[t] = sc + bl[t];
    }

    // W^T bf16 hi/lo for layers 1,2: g_wt[l][n][k] = W[l+1][k][n]
    for (int idx = t; idx < 2 * H_ * H_; idx += blockDim.x) {
        int l = idx >> 14, rem = idx & 16383;
        int k = rem >> 7, n = rem & 127;
        float v = Wl[(l + 1) * H_ * H_ + k * H_ + n];
        __nv_bfloat16 h = __float2bfloat16(v);
        __nv_bfloat16 lo = __float2bfloat16(v - __bfloat162float(h));
        g_wthi[l * 16384 + n * 128 + k] = __bfloat16_as_ushort(h);
        g_wtlo[l * 16384 + n * 128 + k] = __bfloat16_as_ushort(lo);
    }
}

// ---------------------------------------------------------------------------
// Wc1 converter: transpose [8192,128] fp32 -> [128][8192] bf16 hi/lo.
// ---------------------------------------------------------------------------
__global__ __launch_bounds__(256) void wc1_conv_kernel(const float* __restrict__ Wc1)
{
    __shared__ u16 s_hi[64 * 130];
    __shared__ u16 s_lo[64 * 130];
    const int t = threadIdx.x;
    const int k0 = blockIdx.x * 64;

    #pragma unroll
    for (int i = 0; i < 32; i++) {
        int idx = t + i * 256;
        int kk = idx >> 7, n = idx & 127;
        float v = Wc1[(size_t)(k0 + kk) * 128 + n];
        __nv_bfloat16 h = __float2bfloat16(v);
        __nv_bfloat16 l = __float2bfloat16(v - __bfloat162float(h));
        s_hi[kk * 130 + n] = __bfloat16_as_ushort(h);
        s_lo[kk * 130 + n] = __bfloat16_as_ushort(l);
    }
    __syncthreads();

    const u16* src = (t < 128) ? s_hi : s_lo;
    u16* dst = ((t < 128) ? g_bhi : g_blo);
    int n = t & 127;
    dst += (size_t)n * 8192 + k0;
    #pragma unroll
    for (int gblk = 0; gblk < 8; gblk++) {
        u16 tmp[8];
        #pragma unroll
        for (int j = 0; j < 8; j++) tmp[j] = src[(gblk * 8 + j) * 130 + n];
        *(uint4*)(dst + gblk * 8) = *(uint4*)tmp;
    }
}

// ---------------------------------------------------------------------------
// Fused GNN: one CTA per batch element. GEMM on tensor cores via mma.sync
// bf16 3-term split; A built per-lane from fp32 sh_h; B (W^T) from global.
// ---------------------------------------------------------------------------
__global__ __launch_bounds__(256) void gnn_kernel(
    const float* __restrict__ x,
    const float* __restrict__ w_enc,
    const float* __restrict__ b_enc,
    const float* __restrict__ Wl,
    const float* __restrict__ bl)
{
    extern __shared__ float sm[];
    float* sh_h  = sm;                        // 64 x P_ (8448)
    float* sh_hn = sm + 64 * P_;              // 64 x 128 (8192)
    float* sh_xr = sh_hn + 8192;              // 64
    float* sh_g  = sh_xr + 64;                // 64
    float* sh_s1 = sh_g  + 64;                // 64
    float* sh_wl = sh_s1 + 64;                // 1024
    int*   sh_off  = (int*)(sh_wl + 1024);    // 68
    int*   sh_srcl = sh_off + 68;             // 1024

    const int b = blockIdx.x;
    const int t = threadIdx.x;

    if (t < 64) { sh_xr[t] = x[b * 64 + t]; sh_s1[t] = g_s1[t]; }
    if (t <= N_) sh_off[t] = g_off[t];
    #pragma unroll
    for (int i = 0; i < 4; i++) {
        int e = t + i * 256;
        sh_srcl[e] = g_srcl[e];
        sh_wl[e]   = g_wl[e];
    }
    __syncthreads();

    if (t < 64) {
        float acc = 0.f;
        int e0 = sh_off[t], e1 = sh_off[t + 1];
        for (int e = e0; e < e1; e++) acc += sh_wl[e] * sh_xr[sh_srcl[e]];
        sh_g[t] = acc;
    }
    __syncthreads();

    // Layer 0 (rank-1 shortcut)
    for (int idx = t; idx < 8192; idx += 256) {
        int n = idx >> 7, k = idx & 127;
        float v = sh_xr[n] * __ldg(&w_enc[k]) + __ldg(&b_enc[k])
                + sh_g[n] * __ldg(&g_u[k]) + sh_s1[n] * __ldg(&g_c[k]);
        sh_h[n * P_ + k] = fmaxf(v, 0.f);
    }
    __syncthreads();

    const int wid = t >> 5, lane = t & 31;
    const int lg = lane >> 2, lt = lane & 3;     // fragment group / in-group
    const int rm0 = 32 * (wid & 1);              // warp rows
    const int cn0 = 32 * (wid >> 1);             // warp cols

    for (int l = 1; l < 3; l++) {
        const u16* BThi = g_wthi + (l - 1) * 16384;
        const u16* BTlo = g_wtlo + (l - 1) * 16384;
        const float* bb = bl + l * H_;

        // accum [mt][nt][4]
        float c[2][4][4];
        #pragma unroll
        for (int mt = 0; mt < 2; mt++)
            #pragma unroll
            for (int nt = 0; nt < 4; nt++) {
                int col = cn0 + 8 * nt + 2 * lt;
                c[mt][nt][0] = bb[col];
                c[mt][nt][1] = bb[col + 1];
                c[mt][nt][2] = bb[col];
                c[mt][nt][3] = bb[col + 1];
            }

        #pragma unroll
        for (int kb = 0; kb < 8; kb++) {
            const int ck = 16 * kb + 2 * lt;
            u32 ahi[2][4], alo[2][4];
            #pragma unroll
            for (int mt = 0; mt < 2; mt++) {
                int r0 = rm0 + 16 * mt + lg, r1 = r0 + 8;
                float2 p00 = *(const float2*)&sh_h[r0 * P_ + ck];
                float2 p10 = *(const float2*)&sh_h[r1 * P_ + ck];
                float2 p01 = *(const float2*)&sh_h[r0 * P_ + ck + 8];
                float2 p11 = *(const float2*)&sh_h[r1 * P_ + ck + 8];
                split2(p00.x, p00.y, ahi[mt][0], alo[mt][0]);
                split2(p10.x, p10.y, ahi[mt][1], alo[mt][1]);
                split2(p01.x, p01.y, ahi[mt][2], alo[mt][2]);
                split2(p11.x, p11.y, ahi[mt][3], alo[mt][3]);
            }
            #pragma unroll
            for (int nt = 0; nt < 4; nt++) {
                int n = cn0 + 8 * nt + lg;
                int base = n * 128 + 16 * kb + 2 * lt;
                u32 b0h = *(const u32*)(BThi + base);
                u32 b1h = *(const u32*)(BThi + base + 8);
                u32 b0l = *(const u32*)(BTlo + base);
                u32 b1l = *(const u32*)(BTlo + base + 8);
                #pragma unroll
                for (int mt = 0; mt < 2; mt++) {
                    mma_bf16(c[mt][nt][0], c[mt][nt][1], c[mt][nt][2], c[mt][nt][3],
                             ahi[mt][0], ahi[mt][1], ahi[mt][2], ahi[mt][3], b0h, b1h);
                    mma_bf16(c[mt][nt][0], c[mt][nt][1], c[mt][nt][2], c[mt][nt][3],
                             ahi[mt][0], ahi[mt][1], ahi[mt][2], ahi[mt][3], b0l, b1l);
                    mma_bf16(c[mt][nt][0], c[mt][nt][1], c[mt][nt][2], c[mt][nt][3],
                             alo[mt][0], alo[mt][1], alo[mt][2], alo[mt][3], b0h, b1h);
                }
            }
        }

        // write hn
        #pragma unroll
        for (int mt = 0; mt < 2; mt++) {
            int r0 = rm0 + 16 * mt + lg;
            #pragma unroll
            for (int nt = 0; nt < 4; nt++) {
                int col = cn0 + 8 * nt + 2 * lt;
                *(float2*)&sh_hn[r0 * 128 + col] =
                    make_float2(c[mt][nt][0], c[mt][nt][1]);
                *(float2*)&sh_hn[(r0 + 8) * 128 + col] =
                    make_float2(c[mt][nt][2], c[mt][nt][3]);
            }
        }
        __syncthreads();

        // h = relu(h + A @ hn)
        #pragma unroll
        for (int it = 0; it < 16; it++) {
            int idx2 = t + it * 256;
            int d = idx2 >> 6, kp = idx2 & 63;
            ull acc = *(ull*)&sh_h[d * P_ + kp * 2];
            int e0 = sh_off[d], e1 = sh_off[d + 1];
            for (int e = e0; e < e1; e++) {
                ull w2 = pack2(sh_wl[e]);
                acc = fma2(w2, *(ull*)&sh_hn[sh_srcl[e] * 128 + kp * 2], acc);
            }
            float lo, hi; unpack2(acc, lo, hi);
            *(ull*)&sh_h[d * P_ + kp * 2] =
                packpair(fmaxf(lo, 0.f), fmaxf(hi, 0.f));
        }
        __syncthreads();
    }

    // Epilogue: write h_flat as bf16 hi/lo planes
    const size_t base = (size_t)b * 8192;
    #pragma unroll
    for (int i = 0; i < 8; i++) {
        int f = t + i * 256;                  // float4 index
        int n = f >> 5, k4 = f & 31;
        float4 v = *(const float4*)&sh_h[n * P_ + k4 * 4];
        u32 h01, l01, h23, l23;
        split2(v.x, v.y, h01, l01);
        split2(v.z, v.w, h23, l23);
        *(uint2*)(g_ahi + base + f * 4) = make_uint2(h01, h23);
        *(uint2*)(g_alo + base + f * 4) = make_uint2(l01, l23);
    }
}

// ---------------------------------------------------------------------------
// Classifier GEMM: mma.sync bf16 3-term, split-K.
// Grid 256 = 4 K-slices x 64 M-tiles (64 rows). CTA: M=64, N=128, K=2048.
// ---------------------------------------------------------------------------
__global__ __launch_bounds__(256) void cls_mma_kernel()
{
    __shared__ u16 sAhi[64 * 40];
    __shared__ u16 sAlo[64 * 40];
    __shared__ u16 sBhi[128 * 40];
    __shared__ u16 sBlo[128 * 40];

    const int t = threadIdx.x;
    const int wid = t >> 5, lane = t & 31;
    const int lg = lane >> 2, lt = lane & 3;
    const int bx = blockIdx.x;
    const int mt = bx & 63, ks = bx >> 6;
    const int m0 = mt * 64;
    const int kbase = ks * 2048;
    const int warp_m = wid & 3;              // 4 m-tiles of 16
    const int warp_n = wid >> 2;             // 2 n-halves of 64

    const u32 aAhi = smem_u32(sAhi), aAlo = smem_u32(sAlo);
    const u32 aBhi = smem_u32(sBhi), aBlo = smem_u32(sBlo);

    float c[8][4];
    #pragma unroll
    for (int nt = 0; nt < 8; nt++)
        #pragma unroll
        for (int j = 0; j < 4; j++) c[nt][j] = 0.f;

    for (int ch = 0; ch < 64; ch++) {
        const int k0 = kbase + ch * 32;
        __syncthreads();
        {   // A: 64 rows x 32 k, both planes; 256 uint4 per plane
            int m = t >> 2, sg = t & 3;
            size_t ga = (size_t)(m0 + m) * 8192 + k0 + sg * 8;
            *(uint4*)&sAhi[m * 40 + sg * 8] = *(const uint4*)(g_ahi + ga);
            *(uint4*)&sAlo[m * 40 + sg * 8] = *(const uint4*)(g_alo + ga);
            // B: 128 rows x 32 k; 512 uint4 per plane
            #pragma unroll
            for (int i = 0; i < 2; i++) {
                int f = t + i * 256;
                int n = f >> 2, sg2 = f & 3;
                size_t gb = (size_t)n * 8192 + k0 + sg2 * 8;
                *(uint4*)&sBhi[n * 40 + sg2 * 8] = *(const uint4*)(g_bhi + gb);
                *(uint4*)&sBlo[n * 40 + sg2 * 8] = *(const uint4*)(g_blo + gb);
            }
        }
        __syncthreads();

        #pragma unroll
        for (int ks2 = 0; ks2 < 2; ks2++) {
            // A fragments (warp's 16 rows)
            u32 arow = (u32)((16 * warp_m + (lane & 15)) * 40
                             + ks2 * 16 + (lane >> 4) * 8) * 2;
            u32 ahi[4], alo[4];
            ldmx4(ahi[0], ahi[1], ahi[2], ahi[3], aAhi + arow);
            ldmx4(alo[0], alo[1], alo[2], alo[3], aAlo + arow);
            // B fragments: 8 n-tiles via 4 x4-loads per plane
            u32 bhi[8][2], blo[8][2];
            #pragma unroll
            for (int p = 0; p < 4; p++) {
                u32 brow = (u32)((64 * warp_n + 16 * p + (lane & 15)) * 40
                                 + ks2 * 16 + (lane >> 4) * 8) * 2;
                ldmx4(bhi[2 * p][0], bhi[2 * p + 1][0],
                      bhi[2 * p][1], bhi[2 * p + 1][1], aBhi + brow);
                ldmx4(blo[2 * p][0], blo[2 * p + 1][0],
                      blo[2 * p][1], blo[2 * p + 1][1], aBlo + brow);
            }
            #pragma unroll
            for (int nt = 0; nt < 8; nt++) {
                mma_bf16(c[nt][0], c[nt][1], c[nt][2], c[nt][3],
                         ahi[0], ahi[1], ahi[2], ahi[3], bhi[nt][0], bhi[nt][1]);
                mma_bf16(c[nt][0], c[nt][1], c[nt][2], c[nt][3],
                         ahi[0], ahi[1], ahi[2], ahi[3], blo[nt][0], blo[nt][1]);
                mma_bf16(c[nt][0], c[nt][1], c[nt][2], c[nt][3],
                         alo[0], alo[1], alo[2], alo[3], bhi[nt][0], bhi[nt][1]);
            }
        }
    }

    // write partials
    float* part = g_part + (size_t)bx * 8192;
    int r0 = 16 * warp_m + lg;
    #pragma unroll
    for (int nt = 0; nt < 8; nt++) {
        int col = 64 * warp_n + 8 * nt + 2 * lt;
        *(float2*)&part[r0 * 128 + col]       = make_float2(c[nt][0], c[nt][1]);
        *(float2*)&part[(r0 + 8) * 128 + col] = make_float2(c[nt][2], c[nt][3]);
    }
}

// ---------------------------------------------------------------------------
// Reduce: sum 4 K-slices + bc1 + relu -> hidden; logits = hidden@Wc2 + bc2.
// Grid 256 CTAs x 16 batch rows.
// ---------------------------------------------------------------------------
__global__ __launch_bounds__(256) void reduce_kernel(
    const float* __restrict__ bc1,
    const float* __restrict__ Wc2, const float* __restrict__ bc2,
    float* __restrict__ out)
{
    __shared__ float sh_hid[16 * 128];
    const int t = threadIdx.x;
    const int bx = blockIdx.x;

    #pragma unroll
    for (int j = 0; j < 8; j++) {
        int idx = t + j * 256;          // 0..2047
        int mi = idx >> 7, n = idx & 127;
        int m = bx * 16 + mi;
        int mt = m >> 6, mrem = m & 63;
        float s = 0.f;
        #pragma unroll
        for (int ksl = 0; ksl < 4; ksl++)
            s += g_part[(size_t)((ksl << 6) + mt) * 8192 + mrem * 128 + n];
        sh_hid[mi * 128 + n] = fmaxf(s + __ldg(&bc1[n]), 0.f);
    }
    __syncthreads();

    if (t < 32) {
        int r = t >> 1, o = t & 1;
        float s = bc2[o];
        #pragma unroll 4
        for (int k = 0; k < 128; k++)
            s += sh_hid[r * 128 + k] * __ldg(&Wc2[k * 2 + o]);
        out[(bx * 16 + r) * 2 + o] = s;
    }
}

// ---------------------------------------------------------------------------
// Launch
// ---------------------------------------------------------------------------
extern "C" void kernel_launch(void* const* d_in, const int* in_sizes, int n_in,
                              void* d_out, int out_size)
{
    const float* x     = (const float*)d_in[0];
    const void*  ei    = d_in[1];
    const float* ea    = (const float*)d_in[2];
    const float* w_enc = (const float*)d_in[3];
    const float* b_enc = (const float*)d_in[4];
    const float* Wl    = (const float*)d_in[5];
    const float* bl    = (const float*)d_in[6];
    const float* Wc1   = (const float*)d_in[7];
    const float* bc1   = (const float*)d_in[8];
    const float* Wc2   = (const float*)d_in[9];
    const float* bc2   = (const float*)d_in[10];
    float* out = (float*)d_out;

    // floats: 64*P_ + 8192 + 64*3 + 1024 = 17856 ; ints: 68 + 1024 = 1092
    const int gnn_smem = (64 * P_ + 8192 + 192 + 1024 + 1092) * (int)sizeof(float);
    cudaFuncSetAttribute(gnn_kernel, cudaFuncAttributeMaxDynamicSharedMemorySize,
                         gnn_smem);

    prep_kernel<<<1, 256>>>(ei, ea, w_enc, b_enc, Wl, bl);
    wc1_conv_kernel<<<128, 256>>>(Wc1);
    gnn_kernel<<<B_, 256, gnn_smem>>>(x, w_enc, b_enc, Wl, bl);
    cls_mma_kernel<<<256, 256>>>();
    reduce_kernel<<<256, 256>>>(bc1, Wc2, bc2, out);
}

// round 6
// speedup vs baseline: 1.6080x; 1.0055x over previous
#include <cuda_runtime.h>
#include <cuda_bf16.h>
#include <cstdint>

// Problem constants (fixed shapes)
#define B_  4096
#define N_  64
#define H_  128
#define E_  1024
#define P_  132   // sh_h row pitch (floats): stride%32=4 -> <=2-way LDS conflicts

typedef unsigned long long ull;
typedef unsigned short u16;
typedef unsigned int u32;

// ---------------------------------------------------------------------------
// Helpers
// ---------------------------------------------------------------------------
__device__ __forceinline__ u32 smem_u32(const void* p) {
    u32 a;
    asm("{ .reg .u64 t; cvta.to.shared.u64 t, %1; cvt.u32.u64 %0, t; }"
        : "=r"(a) : "l"(p));
    return a;
}
// pack two fp32 -> bf16x2 (e0 -> low half, e1 -> high half), round-nearest
__device__ __forceinline__ u32 packbf(float e0, float e1) {
    u32 r;
    asm("cvt.rn.bf16x2.f32 %0, %1, %2;" : "=r"(r) : "f"(e1), "f"(e0));
    return r;
}
// hi/lo split of a pair
__device__ __forceinline__ void split2(float e0, float e1, u32& hi, u32& lo) {
    hi = packbf(e0, e1);
    float h0 = __uint_as_float(hi << 16);
    float h1 = __uint_as_float(hi & 0xffff0000u);
    lo = packbf(e0 - h0, e1 - h1);
}
__device__ __forceinline__ void mma_bf16(float& c0, float& c1, float& c2, float& c3,
                                         u32 a0, u32 a1, u32 a2, u32 a3,
                                         u32 b0, u32 b1) {
    asm volatile(
        "mma.sync.aligned.m16n8k16.row.col.f32.bf16.bf16.f32 "
        "{%0,%1,%2,%3}, {%4,%5,%6,%7}, {%8,%9}, {%0,%1,%2,%3};"
        : "+f"(c0), "+f"(c1), "+f"(c2), "+f"(c3)
        : "r"(a0), "r"(a1), "r"(a2), "r"(a3), "r"(b0), "r"(b1));
}
__device__ __forceinline__ void ldmx4(u32& r0, u32& r1, u32& r2, u32& r3, u32 addr) {
    asm volatile("ldmatrix.sync.aligned.m8n8.x4.shared.b16 {%0,%1,%2,%3}, [%4];"
                 : "=r"(r0), "=r"(r1), "=r"(r2), "=r"(r3) : "r"(addr));
}
// packed f32x2 fma (legalized to 2xFFMA on sm_100; keeps code compact)
__device__ __forceinline__ ull fma2(ull a, ull b, ull c) {
    ull d;
    asm("fma.rn.f32x2 %0, %1, %2, %3;" : "=l"(d) : "l"(a), "l"(b), "l"(c));
    return d;
}
__device__ __forceinline__ ull pack2(float v) {
    ull d; asm("mov.b64 %0, {%1, %1};" : "=l"(d) : "f"(v)); return d;
}
__device__ __forceinline__ ull packpair(float lo, float hi) {
    ull d; asm("mov.b64 %0, {%1, %2};" : "=l"(d) : "f"(lo), "f"(hi)); return d;
}
__device__ __forceinline__ void unpack2(ull v, float& lo, float& hi) {
    asm("mov.b64 {%0, %1}, %2;" : "=f"(lo), "=f"(hi) : "l"(v));
}

// ---------------------------------------------------------------------------
// Device-global scratch (alloc-free workaround)
// ---------------------------------------------------------------------------
__device__ int   g_off[N_ + 1];
__device__ int   g_srcl[E_];
__device__ float g_wl[E_];
__device__ float g_s1[N_];
__device__ float g_u[H_];
__device__ float g_c[H_];
__device__ u16   g_ahi[(size_t)B_ * N_ * H_];   // 64 MB bf16 hi of h_flat [m][k]
__device__ u16   g_alo[(size_t)B_ * N_ * H_];   // 64 MB bf16 lo
__device__ u16   g_bhi[(size_t)H_ * 8192];      // Wc1^T hi: [n=128][k=8192]
__device__ u16   g_blo[(size_t)H_ * 8192];      // Wc1^T lo
__device__ u16   g_wthi[2 * H_ * H_];           // W^T (layers 1,2) hi: [l][n][k]
__device__ u16   g_wtlo[2 * H_ * H_];           // lo
__device__ float g_part[(size_t)256 * 64 * 128]; // split-K partials (8 MB)

// ---------------------------------------------------------------------------
// Prep: dtype sniff, deterministic CSR, rank-1 layer-0 fold, W^T bf16 split.
// ---------------------------------------------------------------------------
__global__ void prep_kernel(const void* __restrict__ ei_raw,
                            const float* __restrict__ ea,
                            const float* __restrict__ w_enc,
                            const float* __restrict__ b_enc,
                            const float* __restrict__ Wl,
                            const float* __restrict__ bl)
{
    __shared__ int   s_dst[E_];
    __shared__ int   s_src[E_];
    __shared__ float s_w[E_];
    __shared__ int   s_cnt[N_];
    __shared__ int   s_off[N_ + 1];
    __shared__ int   s_flag;

    const int* e32 = (const int*)ei_raw;
    int t = threadIdx.x;

    if (t == 0) s_flag = 0;
    __syncthreads();
    int any = 0;
    for (int i = 1 + 2 * t; i < 2 * E_; i += 2 * blockDim.x)
        any |= (e32[i] != 0);
    if (any) atomicOr(&s_flag, 1);
    __syncthreads();
    const int is64 = (s_flag == 0);

    for (int e = t; e < E_; e += blockDim.x) {
        s_src[e] = is64 ? e32[2 * e]        : e32[e];
        s_dst[e] = is64 ? e32[2 * (E_ + e)] : e32[E_ + e];
        s_w[e]   = ea[e];
    }
    __syncthreads();

    if (t < N_) {
        int cnt = 0; float sum = 0.f;
        for (int e = 0; e < E_; e++)
            if (s_dst[e] == t) { cnt++; sum += s_w[e]; }
        s_cnt[t] = cnt;
        g_s1[t] = sum;
    }
    __syncthreads();

    if (t == 0) {
        int run = 0;
        for (int d = 0; d < N_; d++) { s_off[d] = run; run += s_cnt[d]; }
        s_off[N_] = run;
    }
    __syncthreads();

    if (t < N_) {
        int p = s_off[t];
        for (int e = 0; e < E_; e++)
            if (s_dst[e] == t) { g_srcl[p] = s_src[e]; g_wl[p] = s_w[e]; p++; }
    }
    if (t <= N_) g_off[t] = s_off[t];

    if (t < H_) {
        float su = 0.f, sc = 0.f;
        for (int h = 0; h < H_; h++) {
            float wv = Wl[h * H_ + t];
            su += w_enc[h] * wv;
            sc += b_enc[h] * wv;
        }
        g_u[t] = su;
        g_c[t] = sc + bl[t];
    }

    // W^T bf16 hi/lo for layers 1,2: g_wt[l][n][k] = W[l+1][k][n]
    for (int idx = t; idx < 2 * H_ * H_; idx += blockDim.x) {
        int l = idx >> 14, rem = idx & 16383;
        int k = rem >> 7, n = rem & 127;
        float v = Wl[(l + 1) * H_ * H_ + k * H_ + n];
        __nv_bfloat16 h = __float2bfloat16(v);
        __nv_bfloat16 lo = __float2bfloat16(v - __bfloat162float(h));
        g_wthi[l * 16384 + n * 128 + k] = __bfloat16_as_ushort(h);
        g_wtlo[l * 16384 + n * 128 + k] = __bfloat16_as_ushort(lo);
    }
}

// ---------------------------------------------------------------------------
// Wc1 converter: transpose [8192,128] fp32 -> [128][8192] bf16 hi/lo.
// ---------------------------------------------------------------------------
__global__ __launch_bounds__(256) void wc1_conv_kernel(const float* __restrict__ Wc1)
{
    __shared__ u16 s_hi[64 * 130];
    __shared__ u16 s_lo[64 * 130];
    const int t = threadIdx.x;
    const int k0 = blockIdx.x * 64;

    #pragma unroll
    for (int i = 0; i < 32; i++) {
        int idx = t + i * 256;
        int kk = idx >> 7, n = idx & 127;
        float v = Wc1[(size_t)(k0 + kk) * 128 + n];
        __nv_bfloat16 h = __float2bfloat16(v);
        __nv_bfloat16 l = __float2bfloat16(v - __bfloat162float(h));
        s_hi[kk * 130 + n] = __bfloat16_as_ushort(h);
        s_lo[kk * 130 + n] = __bfloat16_as_ushort(l);
    }
    __syncthreads();

    const u16* src = (t < 128) ? s_hi : s_lo;
    u16* dst = ((t < 128) ? g_bhi : g_blo);
    int n = t & 127;
    dst += (size_t)n * 8192 + k0;
    #pragma unroll
    for (int gblk = 0; gblk < 8; gblk++) {
        u16 tmp[8];
        #pragma unroll
        for (int j = 0; j < 8; j++) tmp[j] = src[(gblk * 8 + j) * 130 + n];
        *(uint4*)(dst + gblk * 8) = *(uint4*)tmp;
    }
}

// ---------------------------------------------------------------------------
// Fused GNN: one CTA per batch element. GEMM on tensor cores via mma.sync
// bf16 3-term split; A built per-lane from fp32 sh_h; B (W^T) from global.
// ---------------------------------------------------------------------------
__global__ __launch_bounds__(256) void gnn_kernel(
    const float* __restrict__ x,
    const float* __restrict__ w_enc,
    const float* __restrict__ b_enc,
    const float* __restrict__ Wl,
    const float* __restrict__ bl)
{
    extern __shared__ float sm[];
    float* sh_h  = sm;                        // 64 x P_ (8448)
    float* sh_hn = sm + 64 * P_;              // 64 x 128 (8192)
    float* sh_xr = sh_hn + 8192;              // 64
    float* sh_g  = sh_xr + 64;                // 64
    float* sh_s1 = sh_g  + 64;                // 64
    float* sh_wl = sh_s1 + 64;                // 1024
    int*   sh_off  = (int*)(sh_wl + 1024);    // 68
    int*   sh_srcl = sh_off + 68;             // 1024

    const int b = blockIdx.x;
    const int t = threadIdx.x;

    if (t < 64) { sh_xr[t] = x[b * 64 + t]; sh_s1[t] = g_s1[t]; }
    if (t <= N_) sh_off[t] = g_off[t];
    #pragma unroll
    for (int i = 0; i < 4; i++) {
        int e = t + i * 256;
        sh_srcl[e] = g_srcl[e];
        sh_wl[e]   = g_wl[e];
    }
    __syncthreads();

    if (t < 64) {
        float acc = 0.f;
        int e0 = sh_off[t], e1 = sh_off[t + 1];
        for (int e = e0; e < e1; e++) acc += sh_wl[e] * sh_xr[sh_srcl[e]];
        sh_g[t] = acc;
    }
    __syncthreads();

    // Layer 0 (rank-1 shortcut)
    for (int idx = t; idx < 8192; idx += 256) {
        int n = idx >> 7, k = idx & 127;
        float v = sh_xr[n] * __ldg(&w_enc[k]) + __ldg(&b_enc[k])
                + sh_g[n] * __ldg(&g_u[k]) + sh_s1[n] * __ldg(&g_c[k]);
        sh_h[n * P_ + k] = fmaxf(v, 0.f);
    }
    __syncthreads();

    const int wid = t >> 5, lane = t & 31;
    const int lg = lane >> 2, lt = lane & 3;     // fragment group / in-group
    const int rm0 = 32 * (wid & 1);              // warp rows
    const int cn0 = 32 * (wid >> 1);             // warp cols

    for (int l = 1; l < 3; l++) {
        const u16* BThi = g_wthi + (l - 1) * 16384;
        const u16* BTlo = g_wtlo + (l - 1) * 16384;
        const float* bb = bl + l * H_;

        // accum [mt][nt][4]
        float c[2][4][4];
        #pragma unroll
        for (int mt = 0; mt < 2; mt++)
            #pragma unroll
            for (int nt = 0; nt < 4; nt++) {
                int col = cn0 + 8 * nt + 2 * lt;
                c[mt][nt][0] = bb[col];
                c[mt][nt][1] = bb[col + 1];
                c[mt][nt][2] = bb[col];
                c[mt][nt][3] = bb[col + 1];
            }

        #pragma unroll
        for (int kb = 0; kb < 8; kb++) {
            const int ck = 16 * kb + 2 * lt;
            u32 ahi[2][4], alo[2][4];
            #pragma unroll
            for (int mt = 0; mt < 2; mt++) {
                int r0 = rm0 + 16 * mt + lg, r1 = r0 + 8;
                float2 p00 = *(const float2*)&sh_h[r0 * P_ + ck];
                float2 p10 = *(const float2*)&sh_h[r1 * P_ + ck];
                float2 p01 = *(const float2*)&sh_h[r0 * P_ + ck + 8];
                float2 p11 = *(const float2*)&sh_h[r1 * P_ + ck + 8];
                split2(p00.x, p00.y, ahi[mt][0], alo[mt][0]);
                split2(p10.x, p10.y, ahi[mt][1], alo[mt][1]);
                split2(p01.x, p01.y, ahi[mt][2], alo[mt][2]);
                split2(p11.x, p11.y, ahi[mt][3], alo[mt][3]);
            }
            #pragma unroll
            for (int nt = 0; nt < 4; nt++) {
                int n = cn0 + 8 * nt + lg;
                int base = n * 128 + 16 * kb + 2 * lt;
                u32 b0h = *(const u32*)(BThi + base);
                u32 b1h = *(const u32*)(BThi + base + 8);
                u32 b0l = *(const u32*)(BTlo + base);
                u32 b1l = *(const u32*)(BTlo + base + 8);
                #pragma unroll
                for (int mt = 0; mt < 2; mt++) {
                    mma_bf16(c[mt][nt][0], c[mt][nt][1], c[mt][nt][2], c[mt][nt][3],
                             ahi[mt][0], ahi[mt][1], ahi[mt][2], ahi[mt][3], b0h, b1h);
                    mma_bf16(c[mt][nt][0], c[mt][nt][1], c[mt][nt][2], c[mt][nt][3],
                             ahi[mt][0], ahi[mt][1], ahi[mt][2], ahi[mt][3], b0l, b1l);
                    mma_bf16(c[mt][nt][0], c[mt][nt][1], c[mt][nt][2], c[mt][nt][3],
                             alo[mt][0], alo[mt][1], alo[mt][2], alo[mt][3], b0h, b1h);
                }
            }
        }

        // write hn
        #pragma unroll
        for (int mt = 0; mt < 2; mt++) {
            int r0 = rm0 + 16 * mt + lg;
            #pragma unroll
            for (int nt = 0; nt < 4; nt++) {
                int col = cn0 + 8 * nt + 2 * lt;
                *(float2*)&sh_hn[r0 * 128 + col] =
                    make_float2(c[mt][nt][0], c[mt][nt][1]);
                *(float2*)&sh_hn[(r0 + 8) * 128 + col] =
                    make_float2(c[mt][nt][2], c[mt][nt][3]);
            }
        }
        __syncthreads();

        // h = relu(h + A @ hn)
        #pragma unroll
        for (int it = 0; it < 16; it++) {
            int idx2 = t + it * 256;
            int d = idx2 >> 6, kp = idx2 & 63;
            ull acc = *(ull*)&sh_h[d * P_ + kp * 2];
            int e0 = sh_off[d], e1 = sh_off[d + 1];
            for (int e = e0; e < e1; e++) {
                ull w2 = pack2(sh_wl[e]);
                acc = fma2(w2, *(ull*)&sh_hn[sh_srcl[e] * 128 + kp * 2], acc);
            }
            float lo, hi; unpack2(acc, lo, hi);
            *(ull*)&sh_h[d * P_ + kp * 2] =
                packpair(fmaxf(lo, 0.f), fmaxf(hi, 0.f));
        }
        __syncthreads();
    }

    // Epilogue: write h_flat as bf16 hi/lo planes
    const size_t base = (size_t)b * 8192;
    #pragma unroll
    for (int i = 0; i < 8; i++) {
        int f = t + i * 256;                  // float4 index
        int n = f >> 5, k4 = f & 31;
        float4 v = *(const float4*)&sh_h[n * P_ + k4 * 4];
        u32 h01, l01, h23, l23;
        split2(v.x, v.y, h01, l01);
        split2(v.z, v.w, h23, l23);
        *(uint2*)(g_ahi + base + f * 4) = make_uint2(h01, h23);
        *(uint2*)(g_alo + base + f * 4) = make_uint2(l01, l23);
    }
}

// ---------------------------------------------------------------------------
// Classifier GEMM: mma.sync bf16 3-term, split-K.
// Grid 256 = 4 K-slices x 64 M-tiles (64 rows). CTA: M=64, N=128, K=2048.
// ---------------------------------------------------------------------------
__global__ __launch_bounds__(256) void cls_mma_kernel()
{
    __shared__ u16 sAhi[64 * 40];
    __shared__ u16 sAlo[64 * 40];
    __shared__ u16 sBhi[128 * 40];
    __shared__ u16 sBlo[128 * 40];

    const int t = threadIdx.x;
    const int wid = t >> 5, lane = t & 31;
    const int lg = lane >> 2, lt = lane & 3;
    const int bx = blockIdx.x;
    const int mt = bx & 63, ks = bx >> 6;
    const int m0 = mt * 64;
    const int kbase = ks * 2048;
    const int warp_m = wid & 3;              // 4 m-tiles of 16
    const int warp_n = wid >> 2;             // 2 n-halves of 64

    const u32 aAhi = smem_u32(sAhi), aAlo = smem_u32(sAlo);
    const u32 aBhi = smem_u32(sBhi), aBlo = smem_u32(sBlo);

    float c[8][4];
    #pragma unroll
    for (int nt = 0; nt < 8; nt++)
        #pragma unroll
        for (int j = 0; j < 4; j++) c[nt][j] = 0.f;

    for (int ch = 0; ch < 64; ch++) {
        const int k0 = kbase + ch * 32;
        __syncthreads();
        {   // A: 64 rows x 32 k, both planes; 256 uint4 per plane
            int m = t >> 2, sg = t & 3;
            size_t ga = (size_t)(m0 + m) * 8192 + k0 + sg * 8;
            *(uint4*)&sAhi[m * 40 + sg * 8] = *(const uint4*)(g_ahi + ga);
            *(uint4*)&sAlo[m * 40 + sg * 8] = *(const uint4*)(g_alo + ga);
            // B: 128 rows x 32 k; 512 uint4 per plane
            #pragma unroll
            for (int i = 0; i < 2; i++) {
                int f = t + i * 256;
                int n = f >> 2, sg2 = f & 3;
                size_t gb = (size_t)n * 8192 + k0 + sg2 * 8;
                *(uint4*)&sBhi[n * 40 + sg2 * 8] = *(const uint4*)(g_bhi + gb);
                *(uint4*)&sBlo[n * 40 + sg2 * 8] = *(const uint4*)(g_blo + gb);
            }
        }
        __syncthreads();

        #pragma unroll
        for (int ks2 = 0; ks2 < 2; ks2++) {
            // A fragments (warp's 16 rows)
            u32 arow = (u32)((16 * warp_m + (lane & 15)) * 40
                             + ks2 * 16 + (lane >> 4) * 8) * 2;
            u32 ahi[4], alo[4];
            ldmx4(ahi[0], ahi[1], ahi[2], ahi[3], aAhi + arow);
            ldmx4(alo[0], alo[1], alo[2], alo[3], aAlo + arow);
            // B fragments: 8 n-tiles via 4 x4-loads per plane
            u32 bhi[8][2], blo[8][2];
            #pragma unroll
            for (int p = 0; p < 4; p++) {
                u32 brow = (u32)((64 * warp_n + 16 * p + (lane & 15)) * 40
                                 + ks2 * 16 + (lane >> 4) * 8) * 2;
                ldmx4(bhi[2 * p][0], bhi[2 * p + 1][0],
                      bhi[2 * p][1], bhi[2 * p + 1][1], aBhi + brow);
                ldmx4(blo[2 * p][0], blo[2 * p + 1][0],
                      blo[2 * p][1], blo[2 * p + 1][1], aBlo + brow);
            }
            #pragma unroll
            for (int nt = 0; nt < 8; nt++) {
                mma_bf16(c[nt][0], c[nt][1], c[nt][2], c[nt][3],
                         ahi[0], ahi[1], ahi[2], ahi[3], bhi[nt][0], bhi[nt][1]);
                mma_bf16(c[nt][0], c[nt][1], c[nt][2], c[nt][3],
                         ahi[0], ahi[1], ahi[2], ahi[3], blo[nt][0], blo[nt][1]);
                mma_bf16(c[nt][0], c[nt][1], c[nt][2], c[nt][3],
                         alo[0], alo[1], alo[2], alo[3], bhi[nt][0], bhi[nt][1]);
            }
        }
    }

    // write partials
    float* part = g_part + (size_t)bx * 8192;
    int r0 = 16 * warp_m + lg;
    #pragma unroll
    for (int nt = 0; nt < 8; nt++) {
        int col = 64 * warp_n + 8 * nt + 2 * lt;
        *(float2*)&part[r0 * 128 + col]       = make_float2(c[nt][0], c[nt][1]);
        *(float2*)&part[(r0 + 8) * 128 + col] = make_float2(c[nt][2], c[nt][3]);
    }
}

// ---------------------------------------------------------------------------
// Reduce: sum 4 K-slices + bc1 + relu -> hidden; logits = hidden@Wc2 + bc2.
// Grid 256 CTAs x 16 batch rows.
// ---------------------------------------------------------------------------
__global__ __launch_bounds__(256) void reduce_kernel(
    const float* __restrict__ bc1,
    const float* __restrict__ Wc2, const float* __restrict__ bc2,
    float* __restrict__ out)
{
    __shared__ float sh_hid[16 * 128];
    const int t = threadIdx.x;
    const int bx = blockIdx.x;

    #pragma unroll
    for (int j = 0; j < 8; j++) {
        int idx = t + j * 256;          // 0..2047
        int mi = idx >> 7, n = idx & 127;
        int m = bx * 16 + mi;
        int mt = m >> 6, mrem = m & 63;
        float s = 0.f;
        #pragma unroll
        for (int ksl = 0; ksl < 4; ksl++)
            s += g_part[(size_t)((ksl << 6) + mt) * 8192 + mrem * 128 + n];
        sh_hid[mi * 128 + n] = fmaxf(s + __ldg(&bc1[n]), 0.f);
    }
    __syncthreads();

    if (t < 32) {
        int r = t >> 1, o = t & 1;
        float s = bc2[o];
        #pragma unroll 4
        for (int k = 0; k < 128; k++)
            s += sh_hid[r * 128 + k] * __ldg(&Wc2[k * 2 + o]);
        out[(bx * 16 + r) * 2 + o] = s;
    }
}

// ---------------------------------------------------------------------------
// Launch
// ---------------------------------------------------------------------------
extern "C" void kernel_launch(void* const* d_in, const int* in_sizes, int n_in,
                              void* d_out, int out_size)
{
    const float* x     = (const float*)d_in[0];
    const void*  ei    = d_in[1];
    const float* ea    = (const float*)d_in[2];
    const float* w_enc = (const float*)d_in[3];
    const float* b_enc = (const float*)d_in[4];
    const float* Wl    = (const float*)d_in[5];
    const float* bl    = (const float*)d_in[6];
    const float* Wc1   = (const float*)d_in[7];
    const float* bc1   = (const float*)d_in[8];
    const float* Wc2   = (const float*)d_in[9];
    const float* bc2   = (const float*)d_in[10];
    float* out = (float*)d_out;

    // floats: 64*P_ + 8192 + 64*3 + 1024 = 17856 ; ints: 68 + 1024 = 1092
    const int gnn_smem = (64 * P_ + 8192 + 192 + 1024 + 1092) * (int)sizeof(float);
    cudaFuncSetAttribute(gnn_kernel, cudaFuncAttributeMaxDynamicSharedMemorySize,
                         gnn_smem);

    prep_kernel<<<1, 256>>>(ei, ea, w_enc, b_enc, Wl, bl);
    wc1_conv_kernel<<<128, 256>>>(Wc1);
    gnn_kernel<<<B_, 256, gnn_smem>>>(x, w_enc, b_enc, Wl, bl);
    cls_mma_kernel<<<256, 256>>>();
    reduce_kernel<<<256, 256>>>(bc1, Wc2, bc2, out);
}